// round 14
// baseline (speedup 1.0000x reference)
#include <cuda_runtime.h>

// Problem shape (fixed by the dataset)
#define TT 4096
#define NB 16
#define CC 512
#define NC (NB * CC)            // 8192 columns
#define CHUNK 64
#define NCHUNKS (TT / CHUNK)    // 64
#define NGRP (NC / 256)         // 32 column groups of 256
#define NBLK (NCHUNKS * NGRP)   // 2048 blocks
#define TOTAL (TT * NC)         // 33,554,432 floats for new_x

// Static scratch (no allocations; reset every replay by k0 — graph-safe)
__device__ float g_agg[NCHUNKS * NC];   // 2 MB: per-(chunk,col) aggregates
__device__ int   g_flag[NBLK];          // per-block "aggregate published"
__device__ float g_rcp[TT * NB];        // 256 KB: 1/(t+1+len_n), [t][n]

// k0: flag reset + reciprocal table.
__global__ void k0_prep(const int* __restrict__ cached_len) {
    int idx = blockIdx.x * blockDim.x + threadIdx.x;
    if (idx < NBLK) g_flag[idx] = 0;
    if (idx < TT * NB) {
        int n = idx & (NB - 1);
        int t = idx >> 4;
        g_rcp[idx] = 1.0f / ((float)(t + 1) + (float)cached_len[n]);
    }
}

// Single-pass scan: register tile, chain-free aggregate lookback, and
// warp-collective polling (warp 0 only — ~19k poll loads/round chip-wide,
// vs ~2M/round when every thread polls; that difference is the whole game).
__global__ void __launch_bounds__(256, 2)
k_main(const float* __restrict__ x,
       const int* __restrict__ cached_len,
       const float* __restrict__ cached_avg,
       float* __restrict__ out, int extras) {
    int bid = blockIdx.x;
    int chunk = bid >> 5;                 // chunk-major: predecessors have lower bid
    int g = bid & (NGRP - 1);
    int tid = threadIdx.x;
    int nc = g * 256 + tid;
    int n = nc >> 9;                      // c fastest, C=512

    // ── Phase 1: stream my tile into registers, compute column sum ──
    const float* px = x + (size_t)chunk * CHUNK * NC + nc;
    float v[CHUNK];
#pragma unroll
    for (int i = 0; i < CHUNK; i++) v[i] = px[(size_t)i * NC];
    float s = 0.0f;
#pragma unroll
    for (int i = 0; i < CHUNK; i++) s += v[i];

    // ── Publish aggregate immediately (chain-free: needs nothing from others) ──
    if (chunk < NCHUNKS - 1) {
        g_agg[chunk * NC + nc] = s;
        __threadfence();                  // release: agg visible before flag
        __syncthreads();                  // all 256 agg stores done before flag
        if (tid == 0) *((volatile int*)&g_flag[bid]) = 1;
    }

    // ── Phase 2: warp-0 collective wait for the ≤63 predecessor flags ──
    if (chunk > 0) {
        if (tid < 32) {
            volatile int* f = g_flag;
            int c0 = tid, c1 = tid + 32;
            int i0 = c0 * NGRP + g, i1 = c1 * NGRP + g;
            bool need0 = (c0 < chunk), need1 = (c1 < chunk);
            for (;;) {
                bool d0 = !need0 || f[i0] != 0;
                bool d1 = !need1 || f[i1] != 0;
                if (__all_sync(0xffffffffu, d0 && d1)) break;
                __nanosleep(64);
            }
        }
        __syncthreads();
        __threadfence();                  // acquire: order flag reads before agg reads
    }

    // ── Fold predecessor aggregates (once, coalesced, L2-resident) ──
    float run = cached_avg[nc] * (float)cached_len[n];
    {
        const float* pa = g_agg + nc;
#pragma unroll 8
        for (int ch = 0; ch < chunk; ch++) run += pa[(size_t)ch * NC];
    }

    // ── Phase 3: rescan registers, scale by rcp, stream out ──
    const float* pr = g_rcp + (size_t)chunk * CHUNK * NB + n;   // warp-uniform
    float*       po = out   + (size_t)chunk * CHUNK * NC + nc;
    float last = 0.0f;
#pragma unroll
    for (int i = 0; i < CHUNK; i++) {
        run += v[i];
        last = run * pr[(size_t)i * NB];
        po[(size_t)i * NC] = last;
    }

    if (extras) {
        // Tuple order: [new_x | new_cached_len (as float) | new_cached_avg]
        if (chunk == NCHUNKS - 1) out[TOTAL + NB + nc] = last;   // new_x[T-1]
        if (bid == 0 && tid < NB) out[TOTAL + tid] = (float)(cached_len[tid] + TT);
    }
}

extern "C" void kernel_launch(void* const* d_in, const int* in_sizes, int n_in,
                              void* d_out, int out_size) {
    const float* x          = (const float*)d_in[0];   // (T, N, C)
    const int*   cached_len = (const int*)d_in[1];     // (N,)
    const float* cached_avg = (const float*)d_in[2];   // (N, C)
    float* out = (float*)d_out;

    int extras = (out_size >= TOTAL + NB + NC) ? 1 : 0;

    k0_prep<<<(TT * NB + 255) / 256, 256>>>(cached_len);
    k_main<<<NBLK, 256>>>(x, cached_len, cached_avg, out, extras);
}

// round 15
// speedup vs baseline: 2.2334x; 2.2334x over previous
#include <cuda_runtime.h>

// Problem shape (fixed by the dataset)
#define TT 4096
#define NB 16
#define CC 512
#define NC (NB * CC)            // 8192 columns
#define NC4 (NC / 4)            // 2048 float4 columns
#define TOTAL (TT * NC)         // 33,554,432 floats for new_x

#define CHUNK 16                // rows per thread
#define NCH (TT / CHUNK)        // 256 chunks
#define SUM_BLOCKS ((NCH * NC4) / 256)   // 2048
#define RCP_BLOCKS ((TT * NB) / 256)     // 256
#define SCAN_BLOCKS (NC4 / 8)            // 256 (8 warps/block, warp per col4)

// Static scratch (no allocations; fully rewritten every replay — graph-safe)
__device__ float4 g_agg[NCH * NC4];    // 8 MB: per-(chunk, col4) sums
__device__ float4 g_base[NCH * NC4];   // 8 MB: seeded exclusive bases
__device__ float  g_rcp[TT * NB];      // 256 KB: 1/(t+1+len_n), [t][n]

__device__ __forceinline__ float4 f4add(float4 a, float4 b) {
    return make_float4(a.x + b.x, a.y + b.y, a.z + b.z, a.w + b.w);
}
__device__ __forceinline__ float4 f4shfl_up(float4 v, int off) {
    v.x = __shfl_up_sync(0xffffffffu, v.x, off);
    v.y = __shfl_up_sync(0xffffffffu, v.y, off);
    v.z = __shfl_up_sync(0xffffffffu, v.z, off);
    v.w = __shfl_up_sync(0xffffffffu, v.w, off);
    return v;
}

// kA: per-(chunk, col4) partial sums (plain loads, chunk-ASCENDING dispatch:
// the high chunks are read last and stay L2-resident for kB) + rcp table role.
__global__ void __launch_bounds__(256)
kA(const float4* __restrict__ x4, const int* __restrict__ cached_len) {
    int bid = blockIdx.x, tid = threadIdx.x;
    if (bid < SUM_BLOCKS) {
        int idx = bid * 256 + tid;                 // 0 .. NCH*NC4-1
        int nc4 = idx & (NC4 - 1);
        int gc = idx >> 11;
        const float4* p = x4 + (size_t)gc * CHUNK * NC4 + nc4;
        float4 s = make_float4(0.f, 0.f, 0.f, 0.f);
#pragma unroll
        for (int i = 0; i < CHUNK; i++) s = f4add(s, p[(size_t)i * NC4]);
        g_agg[gc * NC4 + nc4] = s;
    } else {
        int idx = (bid - SUM_BLOCKS) * 256 + tid;  // 0 .. TT*NB-1
        int n = idx & (NB - 1);
        int t = idx >> 4;
        g_rcp[idx] = 1.0f / ((float)(t + 1) + (float)cached_len[n]);
    }
}

// kscan: warp per col4 column; lane owns 8 consecutive chunks.
// Chain: 8 local adds + 5 shfl steps. Seeds with cached state.
__global__ void __launch_bounds__(256)
kscan(const int* __restrict__ cached_len, const float4* __restrict__ avg4) {
    int col4 = blockIdx.x * 8 + (threadIdx.x >> 5);   // 0 .. NC4-1
    int lane = threadIdx.x & 31;

    float lenf = (float)cached_len[col4 >> 7];
    float4 sa = avg4[col4];
    float4 seed = make_float4(sa.x * lenf, sa.y * lenf, sa.z * lenf, sa.w * lenf);

    float4 a[8];
#pragma unroll
    for (int k = 0; k < 8; k++)
        a[k] = g_agg[(8 * lane + k) * NC4 + col4];

    float4 tot = a[0];
#pragma unroll
    for (int k = 1; k < 8; k++) tot = f4add(tot, a[k]);

    float4 incl = tot;
#pragma unroll
    for (int off = 1; off < 32; off <<= 1) {
        float4 up = f4shfl_up(incl, off);
        if (lane >= off) incl = f4add(incl, up);
    }
    float4 excl = f4shfl_up(incl, 1);
    if (lane == 0) excl = make_float4(0.f, 0.f, 0.f, 0.f);

    float4 run = f4add(seed, excl);
#pragma unroll
    for (int k = 0; k < 8; k++) {
        g_base[(8 * lane + k) * NC4 + col4] = run;
        run = f4add(run, a[k]);
    }
}

// kB: final scan, chunk-DESCENDING dispatch — earliest blocks consume the
// x chunks kA left hot in L2 before kB's own writes cycle them out.
// Hot loop is byte-identical to R13: one g_base load, plain float4 loads,
// warp-uniform rcp, plain stores.
__global__ void __launch_bounds__(256)
kB(const float4* __restrict__ x4, const int* __restrict__ cached_len,
   float4* __restrict__ out4, int extras) {
    int idx = blockIdx.x * 256 + threadIdx.x;      // 0 .. NCH*NC4-1
    int nc4 = idx & (NC4 - 1);
    int gc = (NCH - 1) - (idx >> 11);              // REVERSED chunk order
    int n = nc4 >> 7;                              // warp-uniform

    float4 run = g_base[gc * NC4 + nc4];
    const float4* px = x4   + (size_t)gc * CHUNK * NC4 + nc4;
    float4*       po = out4 + (size_t)gc * CHUNK * NC4 + nc4;
    const float*  pr = g_rcp + (size_t)gc * CHUNK * NB + n;

    float4 last = make_float4(0.f, 0.f, 0.f, 0.f);
#pragma unroll
    for (int i = 0; i < CHUNK; i++) {
        float4 v = px[(size_t)i * NC4];
        run = f4add(run, v);
        float r = pr[(size_t)i * NB];
        last.x = run.x * r; last.y = run.y * r;
        last.z = run.z * r; last.w = run.w * r;
        po[(size_t)i * NC4] = last;
    }

    if (extras) {
        // Tuple order: [new_x | new_cached_len (as float) | new_cached_avg]
        if (gc == NCH - 1)
            out4[(TOTAL + NB) / 4 + nc4] = last;   // new_x[T-1]
        if (idx < NB) {
            float* outf = (float*)out4;
            outf[TOTAL + idx] = (float)(cached_len[idx] + TT);
        }
    }
}

extern "C" void kernel_launch(void* const* d_in, const int* in_sizes, int n_in,
                              void* d_out, int out_size) {
    const float4* x4         = (const float4*)d_in[0];   // (T, N, C)
    const int*    cached_len = (const int*)d_in[1];      // (N,)
    const float4* avg4       = (const float4*)d_in[2];   // (N, C)
    float4* out4 = (float4*)d_out;

    int extras = (out_size >= TOTAL + NB + NC) ? 1 : 0;

    kA<<<SUM_BLOCKS + RCP_BLOCKS, 256>>>(x4, cached_len);
    kscan<<<SCAN_BLOCKS, 256>>>(cached_len, avg4);
    kB<<<SUM_BLOCKS, 256>>>(x4, cached_len, out4, extras);
}

// round 16
// speedup vs baseline: 2.2527x; 1.0087x over previous
#include <cuda_runtime.h>

// Problem shape (fixed by the dataset)
#define TT 4096
#define NB 16
#define CC 512
#define NC (NB * CC)            // 8192 columns
#define NC4 (NC / 4)            // 2048 float4 columns
#define TOTAL (TT * NC)         // 33,554,432 floats for new_x

#define CHUNK 16                // rows per thread
#define NCH (TT / CHUNK)        // 256 chunks
#define SUM_BLOCKS ((NCH * NC4) / 256)   // 2048
#define RCP_BLOCKS ((TT * NB) / 256)     // 256
#define SCAN_BLOCKS (NC4 / 8)            // 256 (8 warps/block, warp per col4)

// Static scratch (no allocations; fully rewritten every replay — graph-safe)
__device__ float4 g_agg[NCH * NC4];    // 8 MB: per-(chunk, col4) sums
__device__ float4 g_base[NCH * NC4];   // 8 MB: seeded exclusive bases
__device__ float  g_rcp[TT * NB];      // 256 KB: 1/(t+1+len_n), [t][n]

__device__ __forceinline__ float4 f4add(float4 a, float4 b) {
    return make_float4(a.x + b.x, a.y + b.y, a.z + b.z, a.w + b.w);
}
__device__ __forceinline__ float4 f4shfl_up(float4 v, int off) {
    v.x = __shfl_up_sync(0xffffffffu, v.x, off);
    v.y = __shfl_up_sync(0xffffffffu, v.y, off);
    v.z = __shfl_up_sync(0xffffffffu, v.z, off);
    v.w = __shfl_up_sync(0xffffffffu, v.w, off);
    return v;
}

// kA: per-(chunk, col4) partial sums (plain loads, chunk-ASCENDING dispatch:
// the high chunks are read last and stay L2-resident for kB) + rcp table role.
__global__ void __launch_bounds__(256)
kA(const float4* __restrict__ x4, const int* __restrict__ cached_len) {
    int bid = blockIdx.x, tid = threadIdx.x;
    if (bid < SUM_BLOCKS) {
        int idx = bid * 256 + tid;                 // 0 .. NCH*NC4-1
        int nc4 = idx & (NC4 - 1);
        int gc = idx >> 11;
        const float4* p = x4 + (size_t)gc * CHUNK * NC4 + nc4;
        float4 s = make_float4(0.f, 0.f, 0.f, 0.f);
#pragma unroll
        for (int i = 0; i < CHUNK; i++) s = f4add(s, p[(size_t)i * NC4]);
        g_agg[gc * NC4 + nc4] = s;
    } else {
        int idx = (bid - SUM_BLOCKS) * 256 + tid;  // 0 .. TT*NB-1
        int n = idx & (NB - 1);
        int t = idx >> 4;
        g_rcp[idx] = 1.0f / ((float)(t + 1) + (float)cached_len[n]);
    }
}

// kscan: warp per col4 column; lane owns 8 consecutive chunks.
// Chain: 8 local adds + 5 shfl steps. Seeds with cached state.
__global__ void __launch_bounds__(256)
kscan(const int* __restrict__ cached_len, const float4* __restrict__ avg4) {
    int col4 = blockIdx.x * 8 + (threadIdx.x >> 5);   // 0 .. NC4-1
    int lane = threadIdx.x & 31;

    float lenf = (float)cached_len[col4 >> 7];
    float4 sa = avg4[col4];
    float4 seed = make_float4(sa.x * lenf, sa.y * lenf, sa.z * lenf, sa.w * lenf);

    float4 a[8];
#pragma unroll
    for (int k = 0; k < 8; k++)
        a[k] = g_agg[(8 * lane + k) * NC4 + col4];

    float4 tot = a[0];
#pragma unroll
    for (int k = 1; k < 8; k++) tot = f4add(tot, a[k]);

    float4 incl = tot;
#pragma unroll
    for (int off = 1; off < 32; off <<= 1) {
        float4 up = f4shfl_up(incl, off);
        if (lane >= off) incl = f4add(incl, up);
    }
    float4 excl = f4shfl_up(incl, 1);
    if (lane == 0) excl = make_float4(0.f, 0.f, 0.f, 0.f);

    float4 run = f4add(seed, excl);
#pragma unroll
    for (int k = 0; k < 8; k++) {
        g_base[(8 * lane + k) * NC4 + col4] = run;
        run = f4add(run, a[k]);
    }
}

// kB: final scan, chunk-DESCENDING dispatch — earliest blocks consume the
// x chunks kA left hot in L2. SINGLE CHANGE vs R15: output stores are
// __stcs (evict-first) so the write-once out stream doesn't allocate L2
// lines and evict the hot x chunks that carry the reuse win.
__global__ void __launch_bounds__(256)
kB(const float4* __restrict__ x4, const int* __restrict__ cached_len,
   float4* __restrict__ out4, int extras) {
    int idx = blockIdx.x * 256 + threadIdx.x;      // 0 .. NCH*NC4-1
    int nc4 = idx & (NC4 - 1);
    int gc = (NCH - 1) - (idx >> 11);              // reversed chunk order
    int n = nc4 >> 7;                              // warp-uniform

    float4 run = g_base[gc * NC4 + nc4];
    const float4* px = x4   + (size_t)gc * CHUNK * NC4 + nc4;
    float4*       po = out4 + (size_t)gc * CHUNK * NC4 + nc4;
    const float*  pr = g_rcp + (size_t)gc * CHUNK * NB + n;

    float4 last = make_float4(0.f, 0.f, 0.f, 0.f);
#pragma unroll
    for (int i = 0; i < CHUNK; i++) {
        float4 v = px[(size_t)i * NC4];            // plain load (proven best)
        run = f4add(run, v);
        float r = pr[(size_t)i * NB];
        last.x = run.x * r; last.y = run.y * r;
        last.z = run.z * r; last.w = run.w * r;
        __stcs(po + (size_t)i * NC4, last);        // evict-first store (the one change)
    }

    if (extras) {
        // Tuple order: [new_x | new_cached_len (as float) | new_cached_avg]
        if (gc == NCH - 1)
            out4[(TOTAL + NB) / 4 + nc4] = last;   // new_x[T-1]
        if (idx < NB) {
            float* outf = (float*)out4;
            outf[TOTAL + idx] = (float)(cached_len[idx] + TT);
        }
    }
}

extern "C" void kernel_launch(void* const* d_in, const int* in_sizes, int n_in,
                              void* d_out, int out_size) {
    const float4* x4         = (const float4*)d_in[0];   // (T, N, C)
    const int*    cached_len = (const int*)d_in[1];      // (N,)
    const float4* avg4       = (const float4*)d_in[2];   // (N, C)
    float4* out4 = (float4*)d_out;

    int extras = (out_size >= TOTAL + NB + NC) ? 1 : 0;

    kA<<<SUM_BLOCKS + RCP_BLOCKS, 256>>>(x4, cached_len);
    kscan<<<SCAN_BLOCKS, 256>>>(cached_len, avg4);
    kB<<<SUM_BLOCKS, 256>>>(x4, cached_len, out4, extras);
}